// round 4
// baseline (speedup 1.0000x reference)
#include <cuda_runtime.h>

// Problem constants (fixed by the dataset: B=32, V=200000, F=400000).
#define BB   32
#define VV   200000
#define FF   400000
#define NV   (BB * VV)      // 6,400,000
#define GB   8              // batches per group (lane sub-group)
#define NGRP (BB / GB)      // 4 groups

// Batch-transposed SoA layouts, index = (g*VV + v)*GB + j  (j = batch within group):
//   xy as float2 -> 8 consecutive lanes cover 64B = 2 full sectors
//   z  as float  -> 8 consecutive lanes cover 32B = 1 full sector
// 3 sectors per vertex-access instead of 4 (float4 wasted w).
__device__ float2 g_vtxXY[NV];
__device__ float  g_vtxZ [NV];
__device__ float2 g_accXY[NV];
__device__ float  g_accZ [NV];

__device__ __forceinline__ void red_add_v2(float2* addr, float x, float y) {
    asm volatile("red.global.add.v2.f32 [%0], {%1, %2};"
                 :: "l"(addr), "f"(x), "f"(y) : "memory");
}
__device__ __forceinline__ void red_add_f(float* addr, float z) {
    asm volatile("red.global.add.f32 [%0], %1;"
                 :: "l"(addr), "f"(z) : "memory");
}

// Smem staging: 8 batch rows x 780 floats (768 data + 12 pad).
#define SROW 780

// ---------------------------------------------------------------------------
// Kernel 1: transpose-repack vertices into SoA arrays and zero accumulators.
// Read phase: 6 x LDG.128 per thread (fully coalesced, DRAM-bound).
// ---------------------------------------------------------------------------
__global__ __launch_bounds__(256) void repack_zero_kernel(const float* __restrict__ verts) {
    __shared__ float s[GB * SROW];
    float4* s4 = reinterpret_cast<float4*>(s);
    const int t  = threadIdx.x;
    const int v0 = blockIdx.x * 256;
    const int g  = blockIdx.y;
    const bool full = (v0 + 256 <= VV);

    if (full) {
#pragma unroll
        for (int rr = 0; rr < 6; rr++) {
            int idx   = rr * 256 + t;          // 0..1535
            int b_loc = idx / 192;
            int k     = idx - b_loc * 192;
            const float4* src = reinterpret_cast<const float4*>(
                verts + (size_t)(g * GB + b_loc) * VV * 3 + (size_t)v0 * 3);
            s4[b_loc * (SROW / 4) + k] = src[k];
        }
    } else {
        for (int r = 0; r < 24; r++) {
            int idx   = r * 256 + t;
            int b_loc = idx / 768;
            int off   = idx - b_loc * 768;
            int vl    = off / 3;
            if (v0 + vl < VV) {
                size_t src = (size_t)(g * GB + b_loc) * VV * 3 + (size_t)(v0 + vl) * 3
                             + (off - vl * 3);
                s[b_loc * SROW + off] = verts[src];
            }
        }
    }
    __syncthreads();

    // Write phase: 2048 (float2 + float) stores, coalesced.
#pragma unroll
    for (int it = 0; it < 8; it++) {
        int w  = it * 256 + t;
        int vl = w >> 3;
        int j  = w & 7;
        int v  = v0 + vl;
        if (v < VV) {
            const float* p = &s[j * SROW + vl * 3];
            size_t dst = ((size_t)g * VV + v) * GB + j;
            g_vtxXY[dst] = make_float2(p[0], p[1]);
            g_vtxZ [dst] = p[2];
            g_accXY[dst] = make_float2(0.0f, 0.0f);
            g_accZ [dst] = 0.0f;
        }
    }
}

// ---------------------------------------------------------------------------
// Kernel 2: accumulate face normals. 2 faces per thread, 8 batch-slots per
// lane sub-group. Gathers front-batched; 18 sector-ops per face-group.
// ---------------------------------------------------------------------------
__global__ __launch_bounds__(256) void accum_kernel(const int* __restrict__ faces) {
    int t  = blockIdx.x * blockDim.x + threadIdx.x;
    int j  = t & 7;
    int fp = t >> 3;
    int f0 = fp * 2;
    int f1 = f0 + 1;
    size_t base = (size_t)blockIdx.y * VV * GB;

    int a0 = __ldg(&faces[3 * f0 + 0]);
    int a1 = __ldg(&faces[3 * f0 + 1]);
    int a2 = __ldg(&faces[3 * f0 + 2]);
    int b0 = __ldg(&faces[3 * f1 + 0]);
    int b1 = __ldg(&faces[3 * f1 + 1]);
    int b2 = __ldg(&faces[3 * f1 + 2]);

    size_t ia0 = base + (size_t)a0 * GB + j;
    size_t ia1 = base + (size_t)a1 * GB + j;
    size_t ia2 = base + (size_t)a2 * GB + j;
    size_t ib0 = base + (size_t)b0 * GB + j;
    size_t ib1 = base + (size_t)b1 * GB + j;
    size_t ib2 = base + (size_t)b2 * GB + j;

    float2 pa0 = g_vtxXY[ia0]; float2 pa1 = g_vtxXY[ia1]; float2 pa2 = g_vtxXY[ia2];
    float2 pb0 = g_vtxXY[ib0]; float2 pb1 = g_vtxXY[ib1]; float2 pb2 = g_vtxXY[ib2];
    float  za0 = g_vtxZ [ia0]; float  za1 = g_vtxZ [ia1]; float  za2 = g_vtxZ [ia2];
    float  zb0 = g_vtxZ [ib0]; float  zb1 = g_vtxZ [ib1]; float  zb2 = g_vtxZ [ib2];

    // Face 0: e1 = v0 - v1; e2 = v2 - v1; n = cross(e2, e1)
    float e1x = pa0.x - pa1.x, e1y = pa0.y - pa1.y, e1z = za0 - za1;
    float e2x = pa2.x - pa1.x, e2y = pa2.y - pa1.y, e2z = za2 - za1;
    float nax = e2y * e1z - e2z * e1y;
    float nay = e2z * e1x - e2x * e1z;
    float naz = e2x * e1y - e2y * e1x;

    // Face 1
    float g1x = pb0.x - pb1.x, g1y = pb0.y - pb1.y, g1z = zb0 - zb1;
    float g2x = pb2.x - pb1.x, g2y = pb2.y - pb1.y, g2z = zb2 - zb1;
    float nbx = g2y * g1z - g2z * g1y;
    float nby = g2z * g1x - g2x * g1z;
    float nbz = g2x * g1y - g2y * g1x;

    red_add_v2(&g_accXY[ia0], nax, nay);  red_add_f(&g_accZ[ia0], naz);
    red_add_v2(&g_accXY[ia1], nax, nay);  red_add_f(&g_accZ[ia1], naz);
    red_add_v2(&g_accXY[ia2], nax, nay);  red_add_f(&g_accZ[ia2], naz);
    red_add_v2(&g_accXY[ib0], nbx, nby);  red_add_f(&g_accZ[ib0], nbz);
    red_add_v2(&g_accXY[ib1], nbx, nby);  red_add_f(&g_accZ[ib1], nbz);
    red_add_v2(&g_accXY[ib2], nbx, nby);  red_add_f(&g_accZ[ib2], nbz);
}

// ---------------------------------------------------------------------------
// Kernel 3: normalize and transpose back to (B, V, 3) packed output.
// Coalesced SoA reads, SMEM stage, 6 x STG.128 per thread.
// ---------------------------------------------------------------------------
__global__ __launch_bounds__(256) void normalize_kernel(float* __restrict__ out) {
    __shared__ float s[GB * SROW];
    float4* s4 = reinterpret_cast<float4*>(s);
    const int t  = threadIdx.x;
    const int v0 = blockIdx.x * 256;
    const int g  = blockIdx.y;
    const bool full = (v0 + 256 <= VV);

#pragma unroll
    for (int it = 0; it < 8; it++) {
        int w  = it * 256 + t;
        int vl = w >> 3;
        int j  = w & 7;
        int v  = v0 + vl;
        if (v < VV) {
            size_t src = ((size_t)g * VV + v) * GB + j;
            float2 a = g_accXY[src];
            float  z = g_accZ [src];
            float sq = a.x * a.x + a.y * a.y + z * z;
            float sc = rsqrtf(fmaxf(sq, 1e-12f));
            float* p = &s[j * SROW + vl * 3];
            p[0] = a.x * sc;
            p[1] = a.y * sc;
            p[2] = z   * sc;
        }
    }
    __syncthreads();

    if (full) {
#pragma unroll
        for (int rr = 0; rr < 6; rr++) {
            int idx   = rr * 256 + t;
            int b_loc = idx / 192;
            int k     = idx - b_loc * 192;
            float4* dst = reinterpret_cast<float4*>(
                out + (size_t)(g * GB + b_loc) * VV * 3 + (size_t)v0 * 3);
            dst[k] = s4[b_loc * (SROW / 4) + k];
        }
    } else {
        for (int r = 0; r < 24; r++) {
            int idx   = r * 256 + t;
            int b_loc = idx / 768;
            int off   = idx - b_loc * 768;
            int vl    = off / 3;
            if (v0 + vl < VV) {
                size_t dst = (size_t)(g * GB + b_loc) * VV * 3 + (size_t)(v0 + vl) * 3
                             + (off - vl * 3);
                out[dst] = s[b_loc * SROW + off];
            }
        }
    }
}

extern "C" void kernel_launch(void* const* d_in, const int* in_sizes, int n_in,
                              void* d_out, int out_size) {
    const float* verts = (const float*)d_in[0];
    const int*   faces = (const int*)d_in[1];
    float*       out   = (float*)d_out;

    dim3 vgrid((VV + 255) / 256, NGRP);          // 782 x 4
    repack_zero_kernel<<<vgrid, 256>>>(verts);

    dim3 agrid((FF * GB / 2) / 256, NGRP);       // 6250 x 4
    accum_kernel<<<agrid, 256>>>(faces);

    normalize_kernel<<<vgrid, 256>>>(out);
}

// round 5
// speedup vs baseline: 1.0346x; 1.0346x over previous
#include <cuda_runtime.h>

// Problem constants (fixed by the dataset: B=32, V=200000, F=400000).
#define BB   32
#define VV   200000
#define FF   400000
#define NV   (BB * VV)      // 6,400,000
#define GB   8              // batches per group (lane sub-group)
#define NGRP (BB / GB)      // 4 groups

// Hybrid layouts (index = (g*VV + v)*GB + j, j = batch-in-group):
//   gathers:  g_vtx4  float4 (1 LDG.128 per vertex, instruction-cheap)
//   scatters: g_accXY float2 + g_accZ float (3 sectors per vertex, sector-cheap)
__device__ float4 g_vtx4 [NV];
__device__ float2 g_accXY[NV];
__device__ float  g_accZ [NV];

__device__ __forceinline__ void red_add_v2(float2* addr, float x, float y) {
    asm volatile("red.global.add.v2.f32 [%0], {%1, %2};"
                 :: "l"(addr), "f"(x), "f"(y) : "memory");
}
__device__ __forceinline__ void red_add_f(float* addr, float z) {
    asm volatile("red.global.add.f32 [%0], %1;"
                 :: "l"(addr), "f"(z) : "memory");
}

// Smem staging: 8 batch rows x 780 floats (768 data + 12 pad).
#define SROW 780

// ---------------------------------------------------------------------------
// Kernel 1: transpose-repack vertices into g_vtx4, zero SoA accumulators.
// ---------------------------------------------------------------------------
__global__ __launch_bounds__(256) void repack_zero_kernel(const float* __restrict__ verts) {
    __shared__ float s[GB * SROW];
    float4* s4 = reinterpret_cast<float4*>(s);
    const int t  = threadIdx.x;
    const int v0 = blockIdx.x * 256;
    const int g  = blockIdx.y;
    const bool full = (v0 + 256 <= VV);

    if (full) {
#pragma unroll
        for (int rr = 0; rr < 6; rr++) {
            int idx   = rr * 256 + t;          // 0..1535
            int b_loc = idx / 192;
            int k     = idx - b_loc * 192;
            const float4* src = reinterpret_cast<const float4*>(
                verts + (size_t)(g * GB + b_loc) * VV * 3 + (size_t)v0 * 3);
            s4[b_loc * (SROW / 4) + k] = src[k];
        }
    } else {
        for (int r = 0; r < 24; r++) {
            int idx   = r * 256 + t;
            int b_loc = idx / 768;
            int off   = idx - b_loc * 768;
            int vl    = off / 3;
            if (v0 + vl < VV) {
                size_t src = (size_t)(g * GB + b_loc) * VV * 3 + (size_t)(v0 + vl) * 3
                             + (off - vl * 3);
                s[b_loc * SROW + off] = verts[src];
            }
        }
    }
    __syncthreads();

#pragma unroll
    for (int it = 0; it < 8; it++) {
        int w  = it * 256 + t;
        int vl = w >> 3;
        int j  = w & 7;
        int v  = v0 + vl;
        if (v < VV) {
            const float* p = &s[j * SROW + vl * 3];
            size_t dst = ((size_t)g * VV + v) * GB + j;
            g_vtx4 [dst] = make_float4(p[0], p[1], p[2], 0.0f);
            g_accXY[dst] = make_float2(0.0f, 0.0f);
            g_accZ [dst] = 0.0f;
        }
    }
}

// ---------------------------------------------------------------------------
// Kernel 2: accumulate face normals. 2 faces per thread.
// Per thread: 3 x LDG.64 (indices) + 6 x LDG.128 (vertices) + 6 x RED.v2
// + 6 x RED.f  =  21 memory instructions, 168 L2 sectors / warp.
// ---------------------------------------------------------------------------
__global__ __launch_bounds__(256) void accum_kernel(const int* __restrict__ faces) {
    int t  = blockIdx.x * blockDim.x + threadIdx.x;
    int j  = t & 7;
    int fp = t >> 3;                    // face-pair index
    size_t base = (size_t)blockIdx.y * VV * GB;

    // 6 consecutive indices for faces (2*fp, 2*fp+1): 3 aligned int2 loads.
    const int2* f2 = reinterpret_cast<const int2*>(faces) + 3 * (size_t)fp;
    int2 q0 = __ldg(&f2[0]);   // a0, a1
    int2 q1 = __ldg(&f2[1]);   // a2, b0
    int2 q2 = __ldg(&f2[2]);   // b1, b2

    size_t ia0 = base + (size_t)q0.x * GB + j;
    size_t ia1 = base + (size_t)q0.y * GB + j;
    size_t ia2 = base + (size_t)q1.x * GB + j;
    size_t ib0 = base + (size_t)q1.y * GB + j;
    size_t ib1 = base + (size_t)q2.x * GB + j;
    size_t ib2 = base + (size_t)q2.y * GB + j;

    float4 va0 = g_vtx4[ia0];
    float4 va1 = g_vtx4[ia1];
    float4 va2 = g_vtx4[ia2];
    float4 vb0 = g_vtx4[ib0];
    float4 vb1 = g_vtx4[ib1];
    float4 vb2 = g_vtx4[ib2];

    // Face A: e1 = v0 - v1; e2 = v2 - v1; n = cross(e2, e1)
    float e1x = va0.x - va1.x, e1y = va0.y - va1.y, e1z = va0.z - va1.z;
    float e2x = va2.x - va1.x, e2y = va2.y - va1.y, e2z = va2.z - va1.z;
    float nax = e2y * e1z - e2z * e1y;
    float nay = e2z * e1x - e2x * e1z;
    float naz = e2x * e1y - e2y * e1x;

    // Face B
    float g1x = vb0.x - vb1.x, g1y = vb0.y - vb1.y, g1z = vb0.z - vb1.z;
    float g2x = vb2.x - vb1.x, g2y = vb2.y - vb1.y, g2z = vb2.z - vb1.z;
    float nbx = g2y * g1z - g2z * g1y;
    float nby = g2z * g1x - g2x * g1z;
    float nbz = g2x * g1y - g2y * g1x;

    red_add_v2(&g_accXY[ia0], nax, nay);  red_add_f(&g_accZ[ia0], naz);
    red_add_v2(&g_accXY[ia1], nax, nay);  red_add_f(&g_accZ[ia1], naz);
    red_add_v2(&g_accXY[ia2], nax, nay);  red_add_f(&g_accZ[ia2], naz);
    red_add_v2(&g_accXY[ib0], nbx, nby);  red_add_f(&g_accZ[ib0], nbz);
    red_add_v2(&g_accXY[ib1], nbx, nby);  red_add_f(&g_accZ[ib1], nbz);
    red_add_v2(&g_accXY[ib2], nbx, nby);  red_add_f(&g_accZ[ib2], nbz);
}

// ---------------------------------------------------------------------------
// Kernel 3: normalize and transpose back to (B, V, 3) packed output.
// ---------------------------------------------------------------------------
__global__ __launch_bounds__(256) void normalize_kernel(float* __restrict__ out) {
    __shared__ float s[GB * SROW];
    float4* s4 = reinterpret_cast<float4*>(s);
    const int t  = threadIdx.x;
    const int v0 = blockIdx.x * 256;
    const int g  = blockIdx.y;
    const bool full = (v0 + 256 <= VV);

#pragma unroll
    for (int it = 0; it < 8; it++) {
        int w  = it * 256 + t;
        int vl = w >> 3;
        int j  = w & 7;
        int v  = v0 + vl;
        if (v < VV) {
            size_t src = ((size_t)g * VV + v) * GB + j;
            float2 a = g_accXY[src];
            float  z = g_accZ [src];
            float sq = a.x * a.x + a.y * a.y + z * z;
            float sc = rsqrtf(fmaxf(sq, 1e-12f));
            float* p = &s[j * SROW + vl * 3];
            p[0] = a.x * sc;
            p[1] = a.y * sc;
            p[2] = z   * sc;
        }
    }
    __syncthreads();

    if (full) {
#pragma unroll
        for (int rr = 0; rr < 6; rr++) {
            int idx   = rr * 256 + t;
            int b_loc = idx / 192;
            int k     = idx - b_loc * 192;
            float4* dst = reinterpret_cast<float4*>(
                out + (size_t)(g * GB + b_loc) * VV * 3 + (size_t)v0 * 3);
            dst[k] = s4[b_loc * (SROW / 4) + k];
        }
    } else {
        for (int r = 0; r < 24; r++) {
            int idx   = r * 256 + t;
            int b_loc = idx / 768;
            int off   = idx - b_loc * 768;
            int vl    = off / 3;
            if (v0 + vl < VV) {
                size_t dst = (size_t)(g * GB + b_loc) * VV * 3 + (size_t)(v0 + vl) * 3
                             + (off - vl * 3);
                out[dst] = s[b_loc * SROW + off];
            }
        }
    }
}

extern "C" void kernel_launch(void* const* d_in, const int* in_sizes, int n_in,
                              void* d_out, int out_size) {
    const float* verts = (const float*)d_in[0];
    const int*   faces = (const int*)d_in[1];
    float*       out   = (float*)d_out;

    dim3 vgrid((VV + 255) / 256, NGRP);          // 782 x 4
    repack_zero_kernel<<<vgrid, 256>>>(verts);

    dim3 agrid((FF * GB / 2) / 256, NGRP);       // 6250 x 4
    accum_kernel<<<agrid, 256>>>(faces);

    normalize_kernel<<<vgrid, 256>>>(out);
}

// round 7
// speedup vs baseline: 1.0901x; 1.0537x over previous
#include <cuda_runtime.h>

// Problem constants (fixed by the dataset: B=32, V=200000, F=400000).
#define BB   32
#define VV   200000
#define FF   400000
#define NV   (BB * VV)      // 6,400,000
#define GB   8              // batches per group (lane sub-group)
#define NGRP (BB / GB)      // 4 groups

// Hybrid layouts (index = (g*VV + v)*GB + j, j = batch-in-group):
//   gathers:  g_vtx4  float4 (1 LDG.128 per vertex, instruction-cheap)
//   scatters: g_accXY float2 + g_accZ float (3 sectors per vertex, sector-cheap)
__device__ float4 g_vtx4 [NV];
__device__ float2 g_accXY[NV];
__device__ float  g_accZ [NV];

__device__ __forceinline__ void red_add_v2(float2* addr, float x, float y) {
    asm volatile("red.global.add.v2.f32 [%0], {%1, %2};"
                 :: "l"(addr), "f"(x), "f"(y) : "memory");
}
__device__ __forceinline__ void red_add_f(float* addr, float z) {
    asm volatile("red.global.add.f32 [%0], %1;"
                 :: "l"(addr), "f"(z) : "memory");
}

// Smem staging: 8 batch rows x 780 floats (768 data + 12 pad).
#define SROW 780
#define VBLOCKS 782          // ceil(VV / 256)
#define ABLOCKS 6250         // FF * GB / 2 / 256

// ---------------------------------------------------------------------------
// Body 1: transpose-repack 256 vertices x 8 batches of group g, zero acc.
// ---------------------------------------------------------------------------
__device__ __forceinline__ void repack_body(const float* __restrict__ verts,
                                            int g, int bx, float* s) {
    float4* s4 = reinterpret_cast<float4*>(s);
    const int t  = threadIdx.x;
    const int v0 = bx * 256;
    const bool full = (v0 + 256 <= VV);

    if (full) {
#pragma unroll
        for (int rr = 0; rr < 6; rr++) {
            int idx   = rr * 256 + t;          // 0..1535
            int b_loc = idx / 192;
            int k     = idx - b_loc * 192;
            const float4* src = reinterpret_cast<const float4*>(
                verts + (size_t)(g * GB + b_loc) * VV * 3 + (size_t)v0 * 3);
            s4[b_loc * (SROW / 4) + k] = src[k];
        }
    } else {
        for (int r = 0; r < 24; r++) {
            int idx   = r * 256 + t;
            int b_loc = idx / 768;
            int off   = idx - b_loc * 768;
            int vl    = off / 3;
            if (v0 + vl < VV) {
                size_t src = (size_t)(g * GB + b_loc) * VV * 3 + (size_t)(v0 + vl) * 3
                             + (off - vl * 3);
                s[b_loc * SROW + off] = verts[src];
            }
        }
    }
    __syncthreads();

#pragma unroll
    for (int it = 0; it < 8; it++) {
        int w  = it * 256 + t;
        int vl = w >> 3;
        int j  = w & 7;
        int v  = v0 + vl;
        if (v < VV) {
            const float* p = &s[j * SROW + vl * 3];
            size_t dst = ((size_t)g * VV + v) * GB + j;
            g_vtx4 [dst] = make_float4(p[0], p[1], p[2], 0.0f);
            g_accXY[dst] = make_float2(0.0f, 0.0f);
            g_accZ [dst] = 0.0f;
        }
    }
}

// ---------------------------------------------------------------------------
// Body 2: accumulate face normals for group g. 2 faces per thread.
// ---------------------------------------------------------------------------
__device__ __forceinline__ void accum_body(const int* __restrict__ faces,
                                           int g, int bx) {
    int t  = bx * 256 + threadIdx.x;
    int j  = t & 7;
    int fp = t >> 3;                    // face-pair index
    size_t base = (size_t)g * VV * GB;

    const int2* f2 = reinterpret_cast<const int2*>(faces) + 3 * (size_t)fp;
    int2 q0 = __ldg(&f2[0]);   // a0, a1
    int2 q1 = __ldg(&f2[1]);   // a2, b0
    int2 q2 = __ldg(&f2[2]);   // b1, b2

    size_t ia0 = base + (size_t)q0.x * GB + j;
    size_t ia1 = base + (size_t)q0.y * GB + j;
    size_t ia2 = base + (size_t)q1.x * GB + j;
    size_t ib0 = base + (size_t)q1.y * GB + j;
    size_t ib1 = base + (size_t)q2.x * GB + j;
    size_t ib2 = base + (size_t)q2.y * GB + j;

    float4 va0 = g_vtx4[ia0];
    float4 va1 = g_vtx4[ia1];
    float4 va2 = g_vtx4[ia2];
    float4 vb0 = g_vtx4[ib0];
    float4 vb1 = g_vtx4[ib1];
    float4 vb2 = g_vtx4[ib2];

    // Face A: e1 = v0 - v1; e2 = v2 - v1; n = cross(e2, e1)
    float e1x = va0.x - va1.x, e1y = va0.y - va1.y, e1z = va0.z - va1.z;
    float e2x = va2.x - va1.x, e2y = va2.y - va1.y, e2z = va2.z - va1.z;
    float nax = e2y * e1z - e2z * e1y;
    float nay = e2z * e1x - e2x * e1z;
    float naz = e2x * e1y - e2y * e1x;

    // Face B
    float g1x = vb0.x - vb1.x, g1y = vb0.y - vb1.y, g1z = vb0.z - vb1.z;
    float g2x = vb2.x - vb1.x, g2y = vb2.y - vb1.y, g2z = vb2.z - vb1.z;
    float nbx = g2y * g1z - g2z * g1y;
    float nby = g2z * g1x - g2x * g1z;
    float nbz = g2x * g1y - g2y * g1x;

    red_add_v2(&g_accXY[ia0], nax, nay);  red_add_f(&g_accZ[ia0], naz);
    red_add_v2(&g_accXY[ia1], nax, nay);  red_add_f(&g_accZ[ia1], naz);
    red_add_v2(&g_accXY[ia2], nax, nay);  red_add_f(&g_accZ[ia2], naz);
    red_add_v2(&g_accXY[ib0], nbx, nby);  red_add_f(&g_accZ[ib0], nbz);
    red_add_v2(&g_accXY[ib1], nbx, nby);  red_add_f(&g_accZ[ib1], nbz);
    red_add_v2(&g_accXY[ib2], nbx, nby);  red_add_f(&g_accZ[ib2], nbz);
}

// ---------------------------------------------------------------------------
// Body 3: normalize group g, transpose back to (B, V, 3) packed output.
// ---------------------------------------------------------------------------
__device__ __forceinline__ void norm_body(float* __restrict__ out,
                                          int g, int bx, float* s) {
    float4* s4 = reinterpret_cast<float4*>(s);
    const int t  = threadIdx.x;
    const int v0 = bx * 256;
    const bool full = (v0 + 256 <= VV);

#pragma unroll
    for (int it = 0; it < 8; it++) {
        int w  = it * 256 + t;
        int vl = w >> 3;
        int j  = w & 7;
        int v  = v0 + vl;
        if (v < VV) {
            size_t src = ((size_t)g * VV + v) * GB + j;
            float2 a = g_accXY[src];
            float  z = g_accZ [src];
            float sq = a.x * a.x + a.y * a.y + z * z;
            float sc = rsqrtf(fmaxf(sq, 1e-12f));
            float* p = &s[j * SROW + vl * 3];
            p[0] = a.x * sc;
            p[1] = a.y * sc;
            p[2] = z   * sc;
        }
    }
    __syncthreads();

    if (full) {
#pragma unroll
        for (int rr = 0; rr < 6; rr++) {
            int idx   = rr * 256 + t;
            int b_loc = idx / 192;
            int k     = idx - b_loc * 192;
            float4* dst = reinterpret_cast<float4*>(
                out + (size_t)(g * GB + b_loc) * VV * 3 + (size_t)v0 * 3);
            dst[k] = s4[b_loc * (SROW / 4) + k];
        }
    } else {
        for (int r = 0; r < 24; r++) {
            int idx   = r * 256 + t;
            int b_loc = idx / 768;
            int off   = idx - b_loc * 768;
            int vl    = off / 3;
            if (v0 + vl < VV) {
                size_t dst = (size_t)(g * GB + b_loc) * VV * 3 + (size_t)(v0 + vl) * 3
                             + (off - vl * 3);
                out[dst] = s[b_loc * SROW + off];
            }
        }
    }
}

// ---------------------------------------------------------------------------
// Fused dispatcher: one launch co-schedules accum(gA) with the independent
// DRAM-bound repack(gR)/norm(gN). DRAM blocks are interleaved 1-in-4 with
// accum blocks (launch order == block index order) so HBM streaming overlaps
// the L2-bound RED traffic across the whole kernel.
// Grid = nA + nR + nN.
// ---------------------------------------------------------------------------
__global__ __launch_bounds__(256) void fused_kernel(
    const float* __restrict__ verts, const int* __restrict__ faces,
    float* __restrict__ out,
    int gA, int nA, int gR, int nR, int gN, int nN) {
    __shared__ float s[GB * SROW];

    int bx = blockIdx.x;
    int D  = nR + nN;
    int d  = -1;          // DRAM-pool job index
    int a  = -1;          // accum job index

    if (nA == 0) {
        d = bx;
    } else if ((bx & 3) == 3 && (bx >> 2) < D) {
        d = bx >> 2;
    } else {
        int before = (bx >> 2) < D ? (bx >> 2) : D;   // dram blocks with index < bx
        a = bx - before;
    }

    if (a >= 0) {
        accum_body(faces, gA, a);
    } else if (d < nR) {
        repack_body(verts, gR, d, s);
    } else {
        norm_body(out, gN, d - nR, s);
    }
}

// ---------------------------------------------------------------------------
// Launch: 6 fused launches on the default stream implement the pipeline
//   L1: repack(0)
//   L2: accum(0) + repack(1)
//   L3: accum(1) + repack(2) + norm(0)
//   L4: accum(2) + repack(3) + norm(1)
//   L5: accum(3) + norm(2)
//   L6: norm(3)
// No streams, no events, no allocations — trivially graph-capturable.
// ---------------------------------------------------------------------------
extern "C" void kernel_launch(void* const* d_in, const int* in_sizes, int n_in,
                              void* d_out, int out_size) {
    const float* verts = (const float*)d_in[0];
    const int*   faces = (const int*)d_in[1];
    float*       out   = (float*)d_out;

    // L1: repack(0)
    fused_kernel<<<VBLOCKS, 256>>>(verts, faces, out, 0, 0, 0, VBLOCKS, 0, 0);
    // L2: accum(0) + repack(1)
    fused_kernel<<<ABLOCKS + VBLOCKS, 256>>>(verts, faces, out,
                                             0, ABLOCKS, 1, VBLOCKS, 0, 0);
    // L3: accum(1) + repack(2) + norm(0)
    fused_kernel<<<ABLOCKS + 2 * VBLOCKS, 256>>>(verts, faces, out,
                                                 1, ABLOCKS, 2, VBLOCKS, 0, VBLOCKS);
    // L4: accum(2) + repack(3) + norm(1)
    fused_kernel<<<ABLOCKS + 2 * VBLOCKS, 256>>>(verts, faces, out,
                                                 2, ABLOCKS, 3, VBLOCKS, 1, VBLOCKS);
    // L5: accum(3) + norm(2)
    fused_kernel<<<ABLOCKS + VBLOCKS, 256>>>(verts, faces, out,
                                             3, ABLOCKS, 0, 0, 2, VBLOCKS);
    // L6: norm(3)
    fused_kernel<<<VBLOCKS, 256>>>(verts, faces, out, 0, 0, 0, 0, 3, VBLOCKS);
}

// round 9
// speedup vs baseline: 1.0945x; 1.0040x over previous
#include <cuda_runtime.h>
#include <stdint.h>

// Problem constants (fixed by the dataset: B=32, V=200000, F=400000).
#define BB   32
#define VV   200000
#define FF   400000
#define NV   (BB * VV)      // 6,400,000
#define GB   8              // batches per group (lane sub-group)
#define NGRP (BB / GB)      // 4 groups

// Hybrid layouts (index = (g*VV + v)*GB + j, j = batch-in-group):
//   gathers:  g_vtx4  float4 (1 LDG.128 per vertex, instruction-cheap)
//   scatters: g_accXY float2 + g_accZ float (3 sectors per vertex, sector-cheap)
__device__ float4 g_vtx4 [NV];
__device__ float2 g_accXY[NV];
__device__ float  g_accZ [NV];

__device__ __forceinline__ void red_add_v2(float2* addr, float x, float y) {
    asm volatile("red.global.add.v2.f32 [%0], {%1, %2};"
                 :: "l"(addr), "f"(x), "f"(y) : "memory");
}
__device__ __forceinline__ void red_add_f(float* addr, float z) {
    asm volatile("red.global.add.f32 [%0], %1;"
                 :: "l"(addr), "f"(z) : "memory");
}

// Smem staging: 8 batch rows x 396 floats (384 data + 12 pad).
// 396 % 4 == 0 (float4 phase alignment); 396 mod 32 == 12 keeps the
// write/read pattern bank = (12j + 3vl + c) % 32 conflict-free.
#define SROW   396
#define VPB    128                      // vertices per DRAM block
#define VBLOCKS ((VV + VPB - 1) / VPB)  // 1563
#define ABLOCKS (FF * GB / 2 / 256)     // 6250

// ---------------------------------------------------------------------------
// Body 1: transpose-repack 128 vertices x 8 batches of group g, zero acc.
// ---------------------------------------------------------------------------
__device__ __forceinline__ void repack_body(const float* __restrict__ verts,
                                            int g, int bx, float* s) {
    float4* s4 = reinterpret_cast<float4*>(s);
    const int t  = threadIdx.x;
    const int v0 = bx * VPB;
    const bool full = (v0 + VPB <= VV);

    if (full) {
        // 8 rows x 96 float4 = 768 float4, 3 per thread.
#pragma unroll
        for (int rr = 0; rr < 3; rr++) {
            int idx   = rr * 256 + t;          // 0..767
            int b_loc = idx / 96;
            int k     = idx - b_loc * 96;
            const float4* src = reinterpret_cast<const float4*>(
                verts + (size_t)(g * GB + b_loc) * VV * 3 + (size_t)v0 * 3);
            s4[b_loc * (SROW / 4) + k] = src[k];
        }
    } else {
        // Tail block: scalar guarded path (8 rows x 384 floats).
        for (int r = 0; r < 12; r++) {
            int idx   = r * 256 + t;           // 0..3071
            int b_loc = idx / 384;
            int off   = idx - b_loc * 384;
            int vl    = off / 3;
            if (v0 + vl < VV) {
                size_t src = (size_t)(g * GB + b_loc) * VV * 3 + (size_t)(v0 + vl) * 3
                             + (off - vl * 3);
                s[b_loc * SROW + off] = verts[src];
            }
        }
    }
    __syncthreads();

    // Write phase: 1024 items, 4 per thread.
#pragma unroll
    for (int it = 0; it < 4; it++) {
        int w  = it * 256 + t;
        int vl = w >> 3;
        int j  = w & 7;
        int v  = v0 + vl;
        if (v < VV) {
            const float* p = &s[j * SROW + vl * 3];
            uint32_t dst = (uint32_t)(g * VV + v) * GB + j;
            g_vtx4 [dst] = make_float4(p[0], p[1], p[2], 0.0f);
            g_accXY[dst] = make_float2(0.0f, 0.0f);
            g_accZ [dst] = 0.0f;
        }
    }
}

// ---------------------------------------------------------------------------
// Body 2: accumulate face normals for group g. 2 faces per thread.
// All offsets 32-bit (max element index 6.4M) to cut register pressure.
// ---------------------------------------------------------------------------
__device__ __forceinline__ void accum_body(const int* __restrict__ faces,
                                           int g, int bx) {
    uint32_t t  = (uint32_t)bx * 256 + threadIdx.x;
    uint32_t j  = t & 7;
    uint32_t fp = t >> 3;               // face-pair index
    uint32_t base = (uint32_t)g * (VV * GB) + j;

    const int2* f2 = reinterpret_cast<const int2*>(faces) + 3 * (size_t)fp;
    int2 q0 = __ldg(&f2[0]);   // a0, a1
    int2 q1 = __ldg(&f2[1]);   // a2, b0
    int2 q2 = __ldg(&f2[2]);   // b1, b2

    uint32_t ia0 = base + (uint32_t)q0.x * GB;
    uint32_t ia1 = base + (uint32_t)q0.y * GB;
    uint32_t ia2 = base + (uint32_t)q1.x * GB;
    uint32_t ib0 = base + (uint32_t)q1.y * GB;
    uint32_t ib1 = base + (uint32_t)q2.x * GB;
    uint32_t ib2 = base + (uint32_t)q2.y * GB;

    float4 va0 = g_vtx4[ia0];
    float4 va1 = g_vtx4[ia1];
    float4 va2 = g_vtx4[ia2];
    float4 vb0 = g_vtx4[ib0];
    float4 vb1 = g_vtx4[ib1];
    float4 vb2 = g_vtx4[ib2];

    // Face A: e1 = v0 - v1; e2 = v2 - v1; n = cross(e2, e1)
    float e1x = va0.x - va1.x, e1y = va0.y - va1.y, e1z = va0.z - va1.z;
    float e2x = va2.x - va1.x, e2y = va2.y - va1.y, e2z = va2.z - va1.z;
    float nax = e2y * e1z - e2z * e1y;
    float nay = e2z * e1x - e2x * e1z;
    float naz = e2x * e1y - e2y * e1x;

    // Face B
    float g1x = vb0.x - vb1.x, g1y = vb0.y - vb1.y, g1z = vb0.z - vb1.z;
    float g2x = vb2.x - vb1.x, g2y = vb2.y - vb1.y, g2z = vb2.z - vb1.z;
    float nbx = g2y * g1z - g2z * g1y;
    float nby = g2z * g1x - g2x * g1z;
    float nbz = g2x * g1y - g2y * g1x;

    red_add_v2(&g_accXY[ia0], nax, nay);  red_add_f(&g_accZ[ia0], naz);
    red_add_v2(&g_accXY[ia1], nax, nay);  red_add_f(&g_accZ[ia1], naz);
    red_add_v2(&g_accXY[ia2], nax, nay);  red_add_f(&g_accZ[ia2], naz);
    red_add_v2(&g_accXY[ib0], nbx, nby);  red_add_f(&g_accZ[ib0], nbz);
    red_add_v2(&g_accXY[ib1], nbx, nby);  red_add_f(&g_accZ[ib1], nbz);
    red_add_v2(&g_accXY[ib2], nbx, nby);  red_add_f(&g_accZ[ib2], nbz);
}

// ---------------------------------------------------------------------------
// Body 3: normalize 128 vertices x 8 batches of group g, write (B, V, 3).
// ---------------------------------------------------------------------------
__device__ __forceinline__ void norm_body(float* __restrict__ out,
                                          int g, int bx, float* s) {
    float4* s4 = reinterpret_cast<float4*>(s);
    const int t  = threadIdx.x;
    const int v0 = bx * VPB;
    const bool full = (v0 + VPB <= VV);

#pragma unroll
    for (int it = 0; it < 4; it++) {
        int w  = it * 256 + t;
        int vl = w >> 3;
        int j  = w & 7;
        int v  = v0 + vl;
        if (v < VV) {
            uint32_t src = (uint32_t)(g * VV + v) * GB + j;
            float2 a = g_accXY[src];
            float  z = g_accZ [src];
            float sq = a.x * a.x + a.y * a.y + z * z;
            float sc = rsqrtf(fmaxf(sq, 1e-12f));
            float* p = &s[j * SROW + vl * 3];
            p[0] = a.x * sc;
            p[1] = a.y * sc;
            p[2] = z   * sc;
        }
    }
    __syncthreads();

    if (full) {
#pragma unroll
        for (int rr = 0; rr < 3; rr++) {
            int idx   = rr * 256 + t;
            int b_loc = idx / 96;
            int k     = idx - b_loc * 96;
            float4* dst = reinterpret_cast<float4*>(
                out + (size_t)(g * GB + b_loc) * VV * 3 + (size_t)v0 * 3);
            dst[k] = s4[b_loc * (SROW / 4) + k];
        }
    } else {
        for (int r = 0; r < 12; r++) {
            int idx   = r * 256 + t;
            int b_loc = idx / 384;
            int off   = idx - b_loc * 384;
            int vl    = off / 3;
            if (v0 + vl < VV) {
                size_t dst = (size_t)(g * GB + b_loc) * VV * 3 + (size_t)(v0 + vl) * 3
                             + (off - vl * 3);
                out[dst] = s[b_loc * SROW + off];
            }
        }
    }
}

// ---------------------------------------------------------------------------
// Fused dispatcher with EXACT interleave ratio K = total / D:
//   DRAM job   <=> (bx % K == K-1) && (bx / K < D);   d = bx / K
//   accum job  otherwise;                              a = bx - min(bx/K, D)
// Guarantees exactly D DRAM jobs and nA accum jobs (a in [0, nA)).
// ---------------------------------------------------------------------------
__global__ __launch_bounds__(256) void fused_kernel(
    const float* __restrict__ verts, const int* __restrict__ faces,
    float* __restrict__ out,
    int gA, int nA, int gR, int nR, int gN, int nN) {
    __shared__ float s[GB * SROW];

    const int bx = blockIdx.x;
    const int D  = nR + nN;
    int d = -1;
    int a = -1;

    if (nA == 0) {
        d = bx;
    } else if (D == 0) {
        a = bx;
    } else {
        const int total = nA + D;
        const int K = total / D;                   // >= 1 since total >= D
        const int q = bx / K;
        if ((bx - q * K) == (K - 1) && q < D) {
            d = q;
        } else {
            a = bx - (q < D ? q : D);
        }
    }

    if (a >= 0) {
        accum_body(faces, gA, a);
    } else if (d < nR) {
        repack_body(verts, gR, d, s);
    } else {
        norm_body(out, gN, d - nR, s);
    }
}

// ---------------------------------------------------------------------------
// Launch: 6 fused launches on the default stream implement the pipeline
//   L1: repack(0)
//   L2: accum(0) + repack(1)
//   L3: accum(1) + repack(2) + norm(0)
//   L4: accum(2) + repack(3) + norm(1)
//   L5: accum(3) + norm(2)
//   L6: norm(3)
// ---------------------------------------------------------------------------
extern "C" void kernel_launch(void* const* d_in, const int* in_sizes, int n_in,
                              void* d_out, int out_size) {
    const float* verts = (const float*)d_in[0];
    const int*   faces = (const int*)d_in[1];
    float*       out   = (float*)d_out;

    // L1: repack(0)
    fused_kernel<<<VBLOCKS, 256>>>(verts, faces, out, 0, 0, 0, VBLOCKS, 0, 0);
    // L2: accum(0) + repack(1)
    fused_kernel<<<ABLOCKS + VBLOCKS, 256>>>(verts, faces, out,
                                             0, ABLOCKS, 1, VBLOCKS, 0, 0);
    // L3: accum(1) + repack(2) + norm(0)
    fused_kernel<<<ABLOCKS + 2 * VBLOCKS, 256>>>(verts, faces, out,
                                                 1, ABLOCKS, 2, VBLOCKS, 0, VBLOCKS);
    // L4: accum(2) + repack(3) + norm(1)
    fused_kernel<<<ABLOCKS + 2 * VBLOCKS, 256>>>(verts, faces, out,
                                                 2, ABLOCKS, 3, VBLOCKS, 1, VBLOCKS);
    // L5: accum(3) + norm(2)
    fused_kernel<<<ABLOCKS + VBLOCKS, 256>>>(verts, faces, out,
                                             3, ABLOCKS, 0, 0, 2, VBLOCKS);
    // L6: norm(3)
    fused_kernel<<<VBLOCKS, 256>>>(verts, faces, out, 0, 0, 0, 0, 3, VBLOCKS);
}

// round 10
// speedup vs baseline: 1.1403x; 1.0419x over previous
#include <cuda_runtime.h>
#include <stdint.h>

// Problem constants (fixed by the dataset: B=32, V=200000, F=400000).
#define BB   32
#define VV   200000
#define FF   400000
#define NV   (BB * VV)      // 6,400,000
#define GB   8              // batches per group (lane sub-group)
#define NGRP (BB / GB)      // 4 groups

// Hybrid layouts (index = (g*VV + v)*GB + j, j = batch-in-group):
//   gathers:  g_vtx4  float4 (1 LDG.128 per vertex, instruction-cheap)
//   scatters: g_accXY float2 + g_accZ float (3 sectors per vertex, sector-cheap)
__device__ float4 g_vtx4 [NV];
__device__ float2 g_accXY[NV];
__device__ float  g_accZ [NV];

__device__ __forceinline__ void red_add_v2(float2* addr, float x, float y) {
    asm volatile("red.global.add.v2.f32 [%0], {%1, %2};"
                 :: "l"(addr), "f"(x), "f"(y) : "memory");
}
__device__ __forceinline__ void red_add_f(float* addr, float z) {
    asm volatile("red.global.add.f32 [%0], %1;"
                 :: "l"(addr), "f"(z) : "memory");
}

// Smem staging: 8 batch rows x 396 floats (384 data + 12 pad).
#define SROW   396
#define VPB    128                      // vertices per DRAM block
#define VBLOCKS ((VV + VPB - 1) / VPB)  // 1563
#define ABLOCKS (FF * GB / 2 / 256)     // 6250

// ---------------------------------------------------------------------------
// Body 1: transpose-repack 128 vertices x 8 batches of group g, zero acc.
// Depends only on kernel inputs -> NO grid-dependency sync (fills the
// predecessor launch's tail waves under PDL).
// ---------------------------------------------------------------------------
__device__ __forceinline__ void repack_body(const float* __restrict__ verts,
                                            int g, int bx, float* s) {
    float4* s4 = reinterpret_cast<float4*>(s);
    const int t  = threadIdx.x;
    const int v0 = bx * VPB;
    const bool full = (v0 + VPB <= VV);

    if (full) {
#pragma unroll
        for (int rr = 0; rr < 3; rr++) {
            int idx   = rr * 256 + t;          // 0..767
            int b_loc = idx / 96;
            int k     = idx - b_loc * 96;
            const float4* src = reinterpret_cast<const float4*>(
                verts + (size_t)(g * GB + b_loc) * VV * 3 + (size_t)v0 * 3);
            s4[b_loc * (SROW / 4) + k] = src[k];
        }
    } else {
        for (int r = 0; r < 12; r++) {
            int idx   = r * 256 + t;           // 0..3071
            int b_loc = idx / 384;
            int off   = idx - b_loc * 384;
            int vl    = off / 3;
            if (v0 + vl < VV) {
                size_t src = (size_t)(g * GB + b_loc) * VV * 3 + (size_t)(v0 + vl) * 3
                             + (off - vl * 3);
                s[b_loc * SROW + off] = verts[src];
            }
        }
    }
    __syncthreads();

#pragma unroll
    for (int it = 0; it < 4; it++) {
        int w  = it * 256 + t;
        int vl = w >> 3;
        int j  = w & 7;
        int v  = v0 + vl;
        if (v < VV) {
            const float* p = &s[j * SROW + vl * 3];
            uint32_t dst = (uint32_t)(g * VV + v) * GB + j;
            g_vtx4 [dst] = make_float4(p[0], p[1], p[2], 0.0f);
            g_accXY[dst] = make_float2(0.0f, 0.0f);
            g_accZ [dst] = 0.0f;
        }
    }
}

// ---------------------------------------------------------------------------
// Body 2: accumulate face normals for group g. 2 faces per thread.
// Needs repack(g) from the PREVIOUS launch -> grid-dependency sync.
// ---------------------------------------------------------------------------
__device__ __forceinline__ void accum_body(const int* __restrict__ faces,
                                           int g, int bx) {
#if __CUDA_ARCH__ >= 900
    cudaGridDependencySynchronize();
#endif
    uint32_t t  = (uint32_t)bx * 256 + threadIdx.x;
    uint32_t j  = t & 7;
    uint32_t fp = t >> 3;               // face-pair index
    uint32_t base = (uint32_t)g * (VV * GB) + j;

    const int2* f2 = reinterpret_cast<const int2*>(faces) + 3 * (size_t)fp;
    int2 q0 = __ldg(&f2[0]);   // a0, a1
    int2 q1 = __ldg(&f2[1]);   // a2, b0
    int2 q2 = __ldg(&f2[2]);   // b1, b2

    uint32_t ia0 = base + (uint32_t)q0.x * GB;
    uint32_t ia1 = base + (uint32_t)q0.y * GB;
    uint32_t ia2 = base + (uint32_t)q1.x * GB;
    uint32_t ib0 = base + (uint32_t)q1.y * GB;
    uint32_t ib1 = base + (uint32_t)q2.x * GB;
    uint32_t ib2 = base + (uint32_t)q2.y * GB;

    float4 va0 = g_vtx4[ia0];
    float4 va1 = g_vtx4[ia1];
    float4 va2 = g_vtx4[ia2];
    float4 vb0 = g_vtx4[ib0];
    float4 vb1 = g_vtx4[ib1];
    float4 vb2 = g_vtx4[ib2];

    // Face A: e1 = v0 - v1; e2 = v2 - v1; n = cross(e2, e1)
    float e1x = va0.x - va1.x, e1y = va0.y - va1.y, e1z = va0.z - va1.z;
    float e2x = va2.x - va1.x, e2y = va2.y - va1.y, e2z = va2.z - va1.z;
    float nax = e2y * e1z - e2z * e1y;
    float nay = e2z * e1x - e2x * e1z;
    float naz = e2x * e1y - e2y * e1x;

    // Face B
    float g1x = vb0.x - vb1.x, g1y = vb0.y - vb1.y, g1z = vb0.z - vb1.z;
    float g2x = vb2.x - vb1.x, g2y = vb2.y - vb1.y, g2z = vb2.z - vb1.z;
    float nbx = g2y * g1z - g2z * g1y;
    float nby = g2z * g1x - g2x * g1z;
    float nbz = g2x * g1y - g2y * g1x;

    red_add_v2(&g_accXY[ia0], nax, nay);  red_add_f(&g_accZ[ia0], naz);
    red_add_v2(&g_accXY[ia1], nax, nay);  red_add_f(&g_accZ[ia1], naz);
    red_add_v2(&g_accXY[ia2], nax, nay);  red_add_f(&g_accZ[ia2], naz);
    red_add_v2(&g_accXY[ib0], nbx, nby);  red_add_f(&g_accZ[ib0], nbz);
    red_add_v2(&g_accXY[ib1], nbx, nby);  red_add_f(&g_accZ[ib1], nbz);
    red_add_v2(&g_accXY[ib2], nbx, nby);  red_add_f(&g_accZ[ib2], nbz);
}

// ---------------------------------------------------------------------------
// Body 3: normalize group g, write (B, V, 3). Needs accum(g) from the
// PREVIOUS launch -> grid-dependency sync.
// ---------------------------------------------------------------------------
__device__ __forceinline__ void norm_body(float* __restrict__ out,
                                          int g, int bx, float* s) {
#if __CUDA_ARCH__ >= 900
    cudaGridDependencySynchronize();
#endif
    float4* s4 = reinterpret_cast<float4*>(s);
    const int t  = threadIdx.x;
    const int v0 = bx * VPB;
    const bool full = (v0 + VPB <= VV);

#pragma unroll
    for (int it = 0; it < 4; it++) {
        int w  = it * 256 + t;
        int vl = w >> 3;
        int j  = w & 7;
        int v  = v0 + vl;
        if (v < VV) {
            uint32_t src = (uint32_t)(g * VV + v) * GB + j;
            float2 a = g_accXY[src];
            float  z = g_accZ [src];
            float sq = a.x * a.x + a.y * a.y + z * z;
            float sc = rsqrtf(fmaxf(sq, 1e-12f));
            float* p = &s[j * SROW + vl * 3];
            p[0] = a.x * sc;
            p[1] = a.y * sc;
            p[2] = z   * sc;
        }
    }
    __syncthreads();

    if (full) {
#pragma unroll
        for (int rr = 0; rr < 3; rr++) {
            int idx   = rr * 256 + t;
            int b_loc = idx / 96;
            int k     = idx - b_loc * 96;
            float4* dst = reinterpret_cast<float4*>(
                out + (size_t)(g * GB + b_loc) * VV * 3 + (size_t)v0 * 3);
            dst[k] = s4[b_loc * (SROW / 4) + k];
        }
    } else {
        for (int r = 0; r < 12; r++) {
            int idx   = r * 256 + t;
            int b_loc = idx / 384;
            int off   = idx - b_loc * 384;
            int vl    = off / 3;
            if (v0 + vl < VV) {
                size_t dst = (size_t)(g * GB + b_loc) * VV * 3 + (size_t)(v0 + vl) * 3
                             + (off - vl * 3);
                out[dst] = s[b_loc * SROW + off];
            }
        }
    }
}

// ---------------------------------------------------------------------------
// Fused dispatcher with EXACT interleave ratio K = total / D (R9-proven).
// Fires the PDL trigger at block entry so the NEXT launch's independent
// (repack) blocks can fill this launch's tail waves.
// ---------------------------------------------------------------------------
__global__ __launch_bounds__(256) void fused_kernel(
    const float* __restrict__ verts, const int* __restrict__ faces,
    float* __restrict__ out,
    int gA, int nA, int gR, int nR, int gN, int nN) {
    __shared__ float s[GB * SROW];

#if __CUDA_ARCH__ >= 900
    cudaTriggerProgrammaticLaunchCompletion();
#endif

    const int bx = blockIdx.x;
    const int D  = nR + nN;
    int d = -1;
    int a = -1;

    if (nA == 0) {
        d = bx;
    } else if (D == 0) {
        a = bx;
    } else {
        const int total = nA + D;
        const int K = total / D;                   // >= 1 since total >= D
        const int q = bx / K;
        if ((bx - q * K) == (K - 1) && q < D) {
            d = q;
        } else {
            a = bx - (q < D ? q : D);
        }
    }

    if (a >= 0) {
        accum_body(faces, gA, a);
    } else if (d < nR) {
        repack_body(verts, gR, d, s);
    } else {
        norm_body(out, gN, d - nR, s);
    }
}

// ---------------------------------------------------------------------------
// Launch: 6 fused launches implement the pipeline; launches 2..6 use PDL so
// their sync-free repack blocks overlap the predecessor's drain.
//   L1: repack(0)
//   L2: accum(0) + repack(1)
//   L3: accum(1) + repack(2) + norm(0)
//   L4: accum(2) + repack(3) + norm(1)
//   L5: accum(3) + norm(2)
//   L6: norm(3)
// ---------------------------------------------------------------------------
static void launch_fused(int grid, bool pdl,
                         const float* verts, const int* faces, float* out,
                         int gA, int nA, int gR, int nR, int gN, int nN) {
    cudaLaunchConfig_t cfg = {};
    cfg.gridDim  = dim3((unsigned)grid, 1, 1);
    cfg.blockDim = dim3(256, 1, 1);
    cfg.dynamicSmemBytes = 0;
    cfg.stream = 0;
    cudaLaunchAttribute attr[1];
    if (pdl) {
        attr[0].id = cudaLaunchAttributeProgrammaticStreamSerialization;
        attr[0].val.programmaticStreamSerializationAllowed = 1;
        cfg.attrs = attr;
        cfg.numAttrs = 1;
    }
    cudaLaunchKernelEx(&cfg, fused_kernel, verts, faces, out,
                       gA, nA, gR, nR, gN, nN);
}

extern "C" void kernel_launch(void* const* d_in, const int* in_sizes, int n_in,
                              void* d_out, int out_size) {
    const float* verts = (const float*)d_in[0];
    const int*   faces = (const int*)d_in[1];
    float*       out   = (float*)d_out;

    // L1: repack(0)  (plain launch; nothing of ours precedes it)
    launch_fused(VBLOCKS, false, verts, faces, out, 0, 0, 0, VBLOCKS, 0, 0);
    // L2: accum(0) + repack(1)
    launch_fused(ABLOCKS + VBLOCKS, true, verts, faces, out,
                 0, ABLOCKS, 1, VBLOCKS, 0, 0);
    // L3: accum(1) + repack(2) + norm(0)
    launch_fused(ABLOCKS + 2 * VBLOCKS, true, verts, faces, out,
                 1, ABLOCKS, 2, VBLOCKS, 0, VBLOCKS);
    // L4: accum(2) + repack(3) + norm(1)
    launch_fused(ABLOCKS + 2 * VBLOCKS, true, verts, faces, out,
                 2, ABLOCKS, 3, VBLOCKS, 1, VBLOCKS);
    // L5: accum(3) + norm(2)
    launch_fused(ABLOCKS + VBLOCKS, true, verts, faces, out,
                 3, ABLOCKS, 0, 0, 2, VBLOCKS);
    // L6: norm(3)
    launch_fused(VBLOCKS, true, verts, faces, out, 0, 0, 0, 0, 3, VBLOCKS);
}